// round 4
// baseline (speedup 1.0000x reference)
#include <cuda_runtime.h>
#include <cuda_bf16.h>

// ---------------------------------------------------------------------------
// GAT 2-layer + softmax head. 6 kernels:
//  1) node1_hist : h1 = x@W1 (f32x2-packed FMA, smem-staged), alphas, + edge
//                  histogram fused in tail
//  2) scanA      : block-wise exclusive scan of degrees
//  3) scanC      : block-prefix fixup (inline scan of block sums), g_cur init,
//                  g_deg re-zeroed for next replay, off[n]=E
//  4) scatter    : CSR column build
//  5) agg_mid    : warp-per-dst softmax-aggregation of layer 1 + fused
//                  (relu, @W2, new alphas) epilogue  -> double-buffered arrays
//  6) agg_out    : same aggregation on layer 2 + fused output head
//                  (relu, @Wout+bout, softmax) -> d_out
// Max-shift in segment softmax skipped (shift-invariant; logits O(1)).
// ---------------------------------------------------------------------------

#define NMAX   100000
#define EMAX   3400000
#define IN_DIM 512
#define HID    16

__device__ __align__(16) float g_h [NMAX * HID];
__device__ __align__(16) float g_h2[NMAX * HID];
__device__ float g_as [NMAX];
__device__ float g_ad [NMAX];
__device__ float g_as2[NMAX];
__device__ float g_ad2[NMAX];

__device__ int g_deg[NMAX];          // static-zero at load; re-zeroed by scanC
__device__ int g_off[NMAX + 1];
__device__ int g_cur[NMAX];
__device__ int g_csr[EMAX];
__device__ int g_bsum[128];

// ---------------------------------------------------------------------------
// packed fp32x2 helpers (sm_100+)
__device__ __forceinline__ unsigned long long dup2(float v) {
    unsigned long long r;
    asm("mov.b64 %0, {%1, %1};" : "=l"(r) : "f"(v));
    return r;
}
__device__ __forceinline__ void fma2(unsigned long long& d,
                                     unsigned long long a, unsigned long long b) {
    asm("fma.rn.f32x2 %0, %1, %2, %0;" : "+l"(d) : "l"(a), "l"(b));
}
__device__ __forceinline__ float2 unpk(unsigned long long v) {
    float2 r;
    asm("mov.b64 {%0, %1}, %2;" : "=f"(r.x), "=f"(r.y) : "l"(v));
    return r;
}

// ---------------------------------------------------------------------------
// Kernel 1: node transform layer 1 + fused edge histogram.
// 128 threads, 256 nodes per block (thread t owns nodes t and t+128).
// dynamic smem: [W1: 8192][avs:16][avd:16][xs: 256*33]
// ---------------------------------------------------------------------------
#define N1T   128
#define N1N   256
#define KT    32
#define XSTR  33
#define SM_W   0
#define SM_AVS 8192
#define SM_AVD 8208
#define SM_XS  8224
#define SM_FLOATS (SM_XS + N1N * XSTR)       // 16672 floats = 66688 B

__global__ void __launch_bounds__(N1T)
node1_hist_kernel(const float* __restrict__ x, const float* __restrict__ W1,
                  const float* __restrict__ a_s, const float* __restrict__ a_d,
                  const int* __restrict__ ei, int n, int E)
{
    extern __shared__ float sm[];
    const int t = threadIdx.x;
    const int node0 = blockIdx.x * N1N;

    // stage W1 (32KB) + alpha vectors once
    for (int j = t; j < IN_DIM * HID / 4; j += N1T)
        ((float4*)(sm + SM_W))[j] = ((const float4*)W1)[j];
    if (t < HID)              sm[SM_AVS + t] = a_s[t];
    else if (t < 2 * HID)     sm[SM_AVD + t - HID] = a_d[t - HID];

    unsigned long long acc0[8], acc1[8];
#pragma unroll
    for (int p = 0; p < 8; p++) { acc0[p] = 0ull; acc1[p] = 0ull; }

    const float4 zero4 = make_float4(0.f, 0.f, 0.f, 0.f);

#pragma unroll 1
    for (int kb = 0; kb < IN_DIM / KT; kb++) {
        __syncthreads();
        // stage x tile: 256 rows x 32 cols, fully coalesced
#pragma unroll
        for (int i = 0; i < 16; i++) {
            int j   = t + N1T * i;            // 0..2047 (float4 units)
            int row = j >> 3;
            int c4  = j & 7;
            int nd  = node0 + row;
            float4 v = (nd < n)
                ? *(const float4*)(x + (size_t)nd * IN_DIM + kb * KT + c4 * 4)
                : zero4;
            float* dp = sm + SM_XS + row * XSTR + c4 * 4;
            dp[0] = v.x; dp[1] = v.y; dp[2] = v.z; dp[3] = v.w;
        }
        __syncthreads();

#pragma unroll 8
        for (int kk = 0; kk < KT; kk++) {
            int k = kb * KT + kk;
            const unsigned long long* wq =
                (const unsigned long long*)(sm + SM_W + k * HID);
            float xv0 = sm[SM_XS + t * XSTR + kk];
            float xv1 = sm[SM_XS + (t + N1T) * XSTR + kk];
            unsigned long long x0 = dup2(xv0);
            unsigned long long x1 = dup2(xv1);
#pragma unroll
            for (int p = 0; p < 8; p++) {
                unsigned long long w = wq[p];
                fma2(acc0[p], x0, w);
                fma2(acc1[p], x1, w);
            }
        }
    }

    // epilogue for the two nodes
#pragma unroll
    for (int which = 0; which < 2; which++) {
        int node = node0 + t + which * N1T;
        if (node < n) {
            unsigned long long* ac = which ? acc1 : acc0;
            float h[HID];
#pragma unroll
            for (int p = 0; p < 8; p++) {
                float2 f = unpk(ac[p]);
                h[2 * p] = f.x; h[2 * p + 1] = f.y;
            }
            float as_v = 0.f, ad_v = 0.f;
#pragma unroll
            for (int c = 0; c < HID; c++) {
                as_v = fmaf(h[c], sm[SM_AVS + c], as_v);
                ad_v = fmaf(h[c], sm[SM_AVD + c], ad_v);
            }
            float4* hp = (float4*)(g_h + (size_t)node * HID);
            hp[0] = make_float4(h[0],  h[1],  h[2],  h[3]);
            hp[1] = make_float4(h[4],  h[5],  h[6],  h[7]);
            hp[2] = make_float4(h[8],  h[9],  h[10], h[11]);
            hp[3] = make_float4(h[12], h[13], h[14], h[15]);
            g_as[node] = as_v;
            g_ad[node] = ad_v;
        }
    }

    // fused histogram (g_deg is zero on entry; re-zeroed by scanC)
    int gtid   = blockIdx.x * N1T + t;
    int stride = gridDim.x * N1T;
    for (int i = gtid; i < E; i += stride)
        atomicAdd(&g_deg[ei[E + i]], 1);
}

// ---------------------------------------------------------------------------
// Kernel 2: block-wise exclusive scan of g_deg -> g_off, block totals -> bsum
// ---------------------------------------------------------------------------
__global__ void __launch_bounds__(1024)
scanA_kernel(int n)
{
    __shared__ int smi[1024];
    int t = threadIdx.x;
    int i = blockIdx.x * 1024 + t;
    int v = (i < n) ? g_deg[i] : 0;
    smi[t] = v;
    __syncthreads();
#pragma unroll
    for (int ofs = 1; ofs < 1024; ofs <<= 1) {
        int add = (t >= ofs) ? smi[t - ofs] : 0;
        __syncthreads();
        smi[t] += add;
        __syncthreads();
    }
    if (i < n) g_off[i] = smi[t] - v;
    if (t == 1023) g_bsum[blockIdx.x] = smi[t];
}

// ---------------------------------------------------------------------------
// Kernel 3: fixup with inline block-sum prefix; init g_cur; re-zero g_deg.
// ---------------------------------------------------------------------------
__global__ void __launch_bounds__(1024)
scanC_kernel(int nb, int n, int E)
{
    __shared__ int pre[128];
    __shared__ int myPre;
    int t = threadIdx.x;
    if (t < 128) pre[t] = (t < nb) ? g_bsum[t] : 0;
    __syncthreads();
    if (t == 0) {
        int s = 0;
        for (int j = 0; j < (int)blockIdx.x; j++) s += pre[j];
        myPre = s;
    }
    __syncthreads();
    int i = blockIdx.x * 1024 + t;
    if (i < n) {
        int o = g_off[i] + myPre;
        g_off[i] = o;
        g_cur[i] = o;
        g_deg[i] = 0;                          // ready for next replay
    }
    if (blockIdx.x == 0 && t == 0) g_off[n] = E;
}

// ---------------------------------------------------------------------------
// Kernel 4: CSR scatter
// ---------------------------------------------------------------------------
__global__ void __launch_bounds__(256)
scatter_kernel(const int* __restrict__ ei, int E)
{
    int i = blockIdx.x * blockDim.x + threadIdx.x;
    if (i < E) {
        int d = ei[E + i];
        int pos = atomicAdd(&g_cur[d], 1);
        g_csr[pos] = ei[i];
    }
}

// ---------------------------------------------------------------------------
// warp-per-dst softmax aggregation core.
// lanes = 2 edges x 16 features; self loop at eidx == deg.
// After return: facc (lane c + lane c+16 both hold acc[c] after caller's
// xor-16 combine), zacc reduced by caller.
// ---------------------------------------------------------------------------
__device__ __forceinline__ void agg_core(
    int d, int lane, const float* __restrict__ hsrc,
    const float* __restrict__ asrc, float ad_d,
    float& facc_o, float& zacc_o)
{
    int begin = g_off[d];
    int deg   = g_off[d + 1] - begin;
    int nE    = deg + 1;
    int c     = lane & 15;
    int half  = lane >> 4;

    float zacc = 0.f, facc = 0.f;

    int fullB = nE >> 5;
    for (int b = 0; b < fullB; b++) {
        int eidx = (b << 5) + lane;
        int s = (eidx < deg) ? __ldg(&g_csr[begin + eidx]) : d;
        float v = __ldg(asrc + s) + ad_d;
        v = (v > 0.f) ? v : 0.2f * v;
        float e = __expf(v);
        zacc += e;
#pragma unroll
        for (int j = 0; j < 16; j++) {
            int   sl = j * 2 + half;
            float e2 = __shfl_sync(0xffffffffu, e, sl);
            int   s2 = __shfl_sync(0xffffffffu, s, sl);
            facc = fmaf(e2, __ldg(hsrc + s2 * HID + c), facc);
        }
    }
    int b0 = fullB << 5;
    if (b0 < nE) {
        int eidx = b0 + lane;
        bool valid = eidx < nE;
        int s = (eidx < deg) ? __ldg(&g_csr[begin + eidx]) : d;
        float v = __ldg(asrc + s) + ad_d;
        v = (v > 0.f) ? v : 0.2f * v;
        float e = valid ? __expf(v) : 0.f;
        zacc += e;
        int iters = (nE - b0 + 1) >> 1;
#pragma unroll 4
        for (int j = 0; j < iters; j++) {
            int   sl = j * 2 + half;
            float e2 = __shfl_sync(0xffffffffu, e, sl);
            int   s2 = __shfl_sync(0xffffffffu, s, sl);
            facc = fmaf(e2, __ldg(hsrc + s2 * HID + c), facc);
        }
    }
    facc_o = facc;
    zacc_o = zacc;
}

#define AGG_WARPS 8

// ---------------------------------------------------------------------------
// Kernel 5: layer-1 aggregation + fused node-mid epilogue -> *2 buffers
// ---------------------------------------------------------------------------
__global__ void __launch_bounds__(AGG_WARPS * 32)
agg_mid_kernel(const float* __restrict__ W2, const float* __restrict__ a_s,
               const float* __restrict__ a_d, const float* __restrict__ b, int n)
{
    __shared__ float Ws[HID * HID];
    __shared__ float avs[HID], avd[HID], bs[HID];
    int t = threadIdx.x;
    if (t < HID * HID) Ws[t] = W2[t];
    if (t < HID) { avs[t] = a_s[t]; avd[t] = a_d[t]; bs[t] = b[t]; }
    __syncthreads();

    int d = blockIdx.x * AGG_WARPS + (t >> 5);
    if (d >= n) return;
    int lane = t & 31;
    int c    = lane & 15;

    float facc, zacc;
    agg_core(d, lane, g_h, g_as, __ldg(&g_ad[d]), facc, zacc);

    facc += __shfl_xor_sync(0xffffffffu, facc, 16);
    zacc += __shfl_xor_sync(0xffffffffu, zacc, 16);
    zacc += __shfl_xor_sync(0xffffffffu, zacc, 8);
    zacc += __shfl_xor_sync(0xffffffffu, zacc, 4);
    zacc += __shfl_xor_sync(0xffffffffu, zacc, 2);
    zacc += __shfl_xor_sync(0xffffffffu, zacc, 1);

    // node-mid epilogue: hin = relu(acc/z + b1); h2 = hin @ W2; new alphas
    float hin = fmaxf(fmaf(facc, 1.f / (zacc + 1e-16f), bs[c]), 0.f);

    float h2 = 0.f;
#pragma unroll
    for (int cc = 0; cc < HID; cc++) {
        float v = __shfl_sync(0xffffffffu, hin, cc);
        h2 = fmaf(v, Ws[cc * HID + c], h2);
    }
    float pa = h2 * avs[c];
    float pd = h2 * avd[c];
#pragma unroll
    for (int ofs = 8; ofs > 0; ofs >>= 1) {
        pa += __shfl_xor_sync(0xffffffffu, pa, ofs);
        pd += __shfl_xor_sync(0xffffffffu, pd, ofs);
    }
    if (lane < HID) g_h2[d * HID + lane] = h2;
    if (lane == 0) { g_as2[d] = pa; g_ad2[d] = pd; }
}

// ---------------------------------------------------------------------------
// Kernel 6: layer-2 aggregation + fused output head (relu, @Wout+bout, softmax)
// ---------------------------------------------------------------------------
__global__ void __launch_bounds__(AGG_WARPS * 32)
agg_out_kernel(const float* __restrict__ Wout, const float* __restrict__ bout,
               const float* __restrict__ b, float* __restrict__ out, int n)
{
    __shared__ float Ws[HID * HID];
    __shared__ float bos[HID], bs[HID];
    int t = threadIdx.x;
    if (t < HID * HID) Ws[t] = Wout[t];
    if (t < HID) { bos[t] = bout[t]; bs[t] = b[t]; }
    __syncthreads();

    int d = blockIdx.x * AGG_WARPS + (t >> 5);
    if (d >= n) return;
    int lane = t & 31;
    int c    = lane & 15;

    float facc, zacc;
    agg_core(d, lane, g_h2, g_as2, __ldg(&g_ad2[d]), facc, zacc);

    facc += __shfl_xor_sync(0xffffffffu, facc, 16);
    zacc += __shfl_xor_sync(0xffffffffu, zacc, 16);
    zacc += __shfl_xor_sync(0xffffffffu, zacc, 8);
    zacc += __shfl_xor_sync(0xffffffffu, zacc, 4);
    zacc += __shfl_xor_sync(0xffffffffu, zacc, 2);
    zacc += __shfl_xor_sync(0xffffffffu, zacc, 1);

    float hin = fmaxf(fmaf(facc, 1.f / (zacc + 1e-16f), bs[c]), 0.f);

    float l = bos[c];
#pragma unroll
    for (int cc = 0; cc < HID; cc++) {
        float v = __shfl_sync(0xffffffffu, hin, cc);
        l = fmaf(v, Ws[cc * HID + c], l);
    }
    // softmax over the 16 classes (within each 16-lane half)
    float m = l;
#pragma unroll
    for (int ofs = 8; ofs > 0; ofs >>= 1)
        m = fmaxf(m, __shfl_xor_sync(0xffffffffu, m, ofs));
    float e = __expf(l - m);
    float ssum = e;
#pragma unroll
    for (int ofs = 8; ofs > 0; ofs >>= 1)
        ssum += __shfl_xor_sync(0xffffffffu, ssum, ofs);

    if (lane < HID) out[(size_t)d * HID + lane] = e / ssum;
}

// ---------------------------------------------------------------------------
extern "C" void kernel_launch(void* const* d_in, const int* in_sizes, int n_in,
                              void* d_out, int out_size)
{
    const float* x    = (const float*)d_in[0];
    const float* W1   = (const float*)d_in[1];
    const float* as1  = (const float*)d_in[2];
    const float* ad1  = (const float*)d_in[3];
    const float* b1   = (const float*)d_in[4];
    const float* W2   = (const float*)d_in[5];
    const float* as2  = (const float*)d_in[6];
    const float* ad2  = (const float*)d_in[7];
    const float* b2   = (const float*)d_in[8];
    const float* Wout = (const float*)d_in[9];
    const float* bout = (const float*)d_in[10];
    const int*   ei   = (const int*)d_in[11];

    int n = in_sizes[0] / IN_DIM;
    int E = in_sizes[11] / 2;
    float* out = (float*)d_out;

    int n1Blocks   = (n + N1N - 1) / N1N;
    int edgeBlocks = (E + 255) / 256;
    int scanBlocks = (n + 1023) / 1024;
    int aggBlocks  = (n + AGG_WARPS - 1) / AGG_WARPS;
    size_t smBytes = SM_FLOATS * sizeof(float);

    cudaFuncSetAttribute(node1_hist_kernel,
                         cudaFuncAttributeMaxDynamicSharedMemorySize,
                         (int)smBytes);

    node1_hist_kernel<<<n1Blocks, N1T, smBytes>>>(x, W1, as1, ad1, ei, n, E);
    scanA_kernel<<<scanBlocks, 1024>>>(n);
    scanC_kernel<<<scanBlocks, 1024>>>(scanBlocks, n, E);
    scatter_kernel<<<edgeBlocks, 256>>>(ei, E);
    agg_mid_kernel<<<aggBlocks, AGG_WARPS * 32>>>(W2, as2, ad2, b1, n);
    agg_out_kernel<<<aggBlocks, AGG_WARPS * 32>>>(Wout, bout, b2, out, n);
}